// round 9
// baseline (speedup 1.0000x reference)
#include <cuda_runtime.h>
#include <cstdint>

// SpatialEncoding: dense 8192x8192 scatter, last-write-wins over 8M edges.
//
// R9: R7 structure (4096 buckets x 2 rows, STAGE_CAP 6) with a restructured
// flush: Phase A allocates all cursors thread-parallel (latency-overlapped
// ATOMG, results in smem), Phase B does warp-cooperative packed stores
// (lanes 0..k-1 of a warp write one bucket's records contiguously -> 1-2
// wavefronts per flush instead of 32-way sector scatter).
// P2 identical to proven R7 (at its smem-atomic floor, ~60us).
//
// Record (8B): hi = ((s&1)<<13) | d ; lo = ((e+1)<<3) | bias_idx
// Max lo per (row,col) == last write wins (keys unique, order-independent).

#define N_NODES    8192
#define BUCKETS    4096          // 2 src-rows per bucket
#define STAGE_CAP  6             // lambda=2 per (bucket,CTA); overflow path below
#define CAP_G      2944          // per-bucket slab (mean 1953, sigma 44 -> +22 sigma)
#define WAVE       8192          // edges per CTA in pass 1
#define P1_THREADS 1024
#define P2_THREADS 512

static __device__ unsigned long long g_bin[(size_t)BUCKETS * CAP_G];  // 96MB
static __device__ int                g_cur[BUCKETS * 8];              // 32B-padded, zero-init

__device__ __forceinline__ void stage_edge(long e, int s, int d, int pl,
                                           unsigned long long* s_stage,
                                           int* s_cnt) {
    int idx = min(max(pl, 1), 5) - 1;                          // 0..4
    unsigned int key = (((unsigned int)e + 1u) << 3) | (unsigned int)idx;
    unsigned long long rec =
        ((unsigned long long)(unsigned int)(((s & 1) << 13) | d) << 32) |
        (unsigned long long)key;
    int bk  = s >> 1;
    int pos = atomicAdd(&s_cnt[bk], 1);
    if (pos < STAGE_CAP) {
        s_stage[bk * STAGE_CAP + pos] = rec;
    } else {
        int gp = atomicAdd(&g_cur[bk * 8], 1);                 // rare overflow
        if (gp < CAP_G)
            g_bin[(size_t)bk * CAP_G + gp] = rec;
    }
}

// ---------------- Pass 1: stage + two-phase flush ----------------
__global__ void __launch_bounds__(P1_THREADS)
bin_kernel(const int* __restrict__ src,
           const int* __restrict__ dst,
           const int* __restrict__ plen,
           long E) {
    extern __shared__ char smem[];
    unsigned long long* s_stage = (unsigned long long*)smem;           // 4096*6*8 = 192KB
    int* s_cnt = (int*)(smem + (size_t)BUCKETS * STAGE_CAP * 8);       // 16KB
    int* s_gp  = s_cnt + BUCKETS;                                      // 16KB

    const int t = threadIdx.x;
    #pragma unroll
    for (int i = 0; i < BUCKETS / P1_THREADS; i++)
        s_cnt[t + i * P1_THREADS] = 0;
    __syncthreads();

    const long base = (long)blockIdx.x * WAVE;
    #pragma unroll
    for (int c = 0; c < WAVE / (P1_THREADS * 4); c++) {
        long e0 = base + (long)c * (P1_THREADS * 4) + (long)t * 4;
        if (e0 + 3 < E) {
            int4 s4 = *reinterpret_cast<const int4*>(&src[e0]);
            int4 d4 = *reinterpret_cast<const int4*>(&dst[e0]);
            int4 p4 = *reinterpret_cast<const int4*>(&plen[e0]);
            stage_edge(e0 + 0, s4.x, d4.x, p4.x, s_stage, s_cnt);
            stage_edge(e0 + 1, s4.y, d4.y, p4.y, s_stage, s_cnt);
            stage_edge(e0 + 2, s4.z, d4.z, p4.z, s_stage, s_cnt);
            stage_edge(e0 + 3, s4.w, d4.w, p4.w, s_stage, s_cnt);
        } else {
            for (long e = e0; e < E && e < e0 + 4; e++)
                stage_edge(e, src[e], dst[e], plen[e], s_stage, s_cnt);
        }
    }
    __syncthreads();

    // Phase A: cursor allocation, thread-parallel (ATOMG latency overlapped)
    #pragma unroll
    for (int i = 0; i < BUCKETS / P1_THREADS; i++) {
        int bk = t + i * P1_THREADS;
        int k = min(s_cnt[bk], STAGE_CAP);
        int gp = 0;
        if (k > 0) gp = atomicAdd(&g_cur[bk * 8], k);
        s_gp[bk] = gp;
    }
    __syncthreads();

    // Phase B: warp-cooperative packed stores (contiguous lanes per bucket)
    const int wid  = t >> 5;
    const int lane = t & 31;
    const int bpw  = BUCKETS / (P1_THREADS / 32);   // buckets per warp = 128
    #pragma unroll 4
    for (int i = 0; i < bpw; i++) {
        int bk = wid * bpw + i;
        int k = min(s_cnt[bk], STAGE_CAP);
        if (k == 0) continue;
        int gp = s_gp[bk];
        if (lane < k && gp + lane < CAP_G)
            g_bin[(size_t)bk * CAP_G + gp + lane] = s_stage[bk * STAGE_CAP + lane];
    }
}

// ---------------- Pass 2: per-bucket resolve + convert (proven R7) --------
__global__ void __launch_bounds__(P2_THREADS, 3)
resolve_kernel(const float* __restrict__ b,
               float* __restrict__ out) {
    extern __shared__ char smem[];
    unsigned int* s_key = (unsigned int*)smem;          // 2*8192*4 = 64KB
    __shared__ float s_b[8];

    const int bk = blockIdx.x;
    const int t  = threadIdx.x;

    // zero 64KB of keys (uint4)
    uint4* kz = (uint4*)s_key;
    #pragma unroll
    for (int i = 0; i < (2 * N_NODES / 4) / P2_THREADS; i++)
        kz[t + i * P2_THREADS] = make_uint4(0u, 0u, 0u, 0u);
    if (t < 8) s_b[t] = (t < 5) ? b[t] : 0.0f;

    int cnt = g_cur[bk * 8];
    if (cnt > CAP_G) cnt = CAP_G;
    __syncthreads();

    // stream records as uint4 (2 records per load); smem atomicMax resolves
    const unsigned long long* __restrict__ recs = &g_bin[(size_t)bk * CAP_G];
    const uint4* __restrict__ recs4 = reinterpret_cast<const uint4*>(recs);
    const int npair = cnt >> 1;
    for (int i = t; i < npair; i += P2_THREADS) {
        uint4 r = recs4[i];
        // record 0: lo=r.x key, hi=r.y addr ; record 1: lo=r.z, hi=r.w
        atomicMax(&s_key[r.y & 0x3FFFu], r.x);
        atomicMax(&s_key[r.w & 0x3FFFu], r.z);
    }
    if (t == 0 && (cnt & 1)) {
        unsigned long long r = recs[cnt - 1];
        atomicMax(&s_key[(unsigned int)(r >> 32) & 0x3FFFu], (unsigned int)r);
    }
    __syncthreads();

    // convert + contiguous 64KB output write (rows bk*2, bk*2+1)
    float* __restrict__ ob = out + (size_t)bk * 2 * N_NODES;
    #pragma unroll
    for (int i = 0; i < (2 * N_NODES / 4) / P2_THREADS; i++) {
        int j4 = t + i * P2_THREADS;
        uint4 k = kz[j4];
        float4 o;
        o.x = k.x ? s_b[k.x & 7u] : 0.0f;
        o.y = k.y ? s_b[k.y & 7u] : 0.0f;
        o.z = k.z ? s_b[k.z & 7u] : 0.0f;
        o.w = k.w ? s_b[k.w & 7u] : 0.0f;
        *reinterpret_cast<float4*>(&ob[j4 * 4]) = o;
    }

    // reset our cursor for the next graph replay (deterministic counts)
    if (t == 0) g_cur[bk * 8] = 0;
}

extern "C" void kernel_launch(void* const* d_in, const int* in_sizes, int n_in,
                              void* d_out, int out_size) {
    // metadata order: x [N,128] f32, src [E] i32, dst [E] i32,
    //                 path_len [E] i32, b [5] f32
    const int*   src  = (const int*)d_in[1];
    const int*   dst  = (const int*)d_in[2];
    const int*   plen = (const int*)d_in[3];
    const float* b    = (const float*)d_in[4];
    float*       out  = (float*)d_out;

    const long E = (long)in_sizes[1];   // 8,000,000

    const size_t p1_smem = (size_t)BUCKETS * STAGE_CAP * 8 + 2 * BUCKETS * 4;  // 224KB
    const size_t p2_smem = (size_t)2 * N_NODES * 4;                            // 64KB

    static bool attr_set = false;
    if (!attr_set) {
        cudaFuncSetAttribute(bin_kernel,
                             cudaFuncAttributeMaxDynamicSharedMemorySize, (int)p1_smem);
        cudaFuncSetAttribute(resolve_kernel,
                             cudaFuncAttributeMaxDynamicSharedMemorySize, (int)p2_smem);
        attr_set = true;
    }

    {
        const int blocks = (int)((E + WAVE - 1) / WAVE);   // 977
        bin_kernel<<<blocks, P1_THREADS, p1_smem>>>(src, dst, plen, E);
    }
    {
        resolve_kernel<<<BUCKETS, P2_THREADS, p2_smem>>>(b, out);
    }
}

// round 10
// speedup vs baseline: 1.3653x; 1.3653x over previous
#include <cuda_runtime.h>
#include <cstdint>

// SpatialEncoding: dense 8192x8192 scatter, last-write-wins over 8M edges.
//
// R10 = proven R7 + pair-packed flush. 4096 buckets x 2 src-rows, STAGE_CAP 6.
//  P1: smem-staged binning; cursor counts PAIRS; flush stores uint4
//      (2 records / 16B STG) -> flush LSU lane-ops halved. Odd counts padded
//      with a zero record (key=0 impossible for real edges).
//  P2: 1 CTA per bucket, 64KB smem -> 3 CTAs/SM; uint4 record loads;
//      atomicMax predicated on key!=0 (padding costs no ATOMS lanes).
//
// Record (8B): hi = ((s&1)<<13) | d ; lo = ((e+1)<<3) | bias_idx
// Max lo per (row,col) == last write wins (keys unique, order-independent).

#define N_NODES    8192
#define BUCKETS    4096          // 2 src-rows per bucket
#define STAGE_CAP  6             // lambda=2 per (bucket,CTA); overflow path below
#define CAP_PAIRS  1856          // per-bucket slab in PAIRS (mean ~1240, +~20 sigma)
#define WAVE       8192          // edges per CTA in pass 1
#define P1_THREADS 1024
#define P2_THREADS 512

static __device__ uint4 g_bin[(size_t)BUCKETS * CAP_PAIRS];   // ~122MB (pairs)
static __device__ int   g_cur[BUCKETS * 8];                   // 32B-padded, zero-init

__device__ __forceinline__ void stage_edge(long e, int s, int d, int pl,
                                           unsigned long long* s_stage,
                                           int* s_cnt) {
    int idx = min(max(pl, 1), 5) - 1;                          // 0..4
    unsigned int key = (((unsigned int)e + 1u) << 3) | (unsigned int)idx;
    unsigned int hi  = (unsigned int)(((s & 1) << 13) | d);
    int bk  = s >> 1;
    int pos = atomicAdd(&s_cnt[bk], 1);
    if (pos < STAGE_CAP) {
        s_stage[bk * STAGE_CAP + pos] =
            ((unsigned long long)hi << 32) | (unsigned long long)key;
    } else {
        // rare overflow: append one pair (record + zero padding)
        int gp = atomicAdd(&g_cur[bk * 8], 1);
        if (gp < CAP_PAIRS)
            g_bin[(size_t)bk * CAP_PAIRS + gp] = make_uint4(key, hi, 0u, 0u);
    }
}

// ---------------- Pass 1: stage + pair-packed flush ----------------
__global__ void __launch_bounds__(P1_THREADS)
bin_kernel(const int* __restrict__ src,
           const int* __restrict__ dst,
           const int* __restrict__ plen,
           long E) {
    extern __shared__ char smem[];
    unsigned long long* s_stage = (unsigned long long*)smem;           // 4096*6*8 = 192KB
    int* s_cnt = (int*)(smem + (size_t)BUCKETS * STAGE_CAP * 8);       // 16KB

    const int t = threadIdx.x;
    #pragma unroll
    for (int i = 0; i < BUCKETS / P1_THREADS; i++)
        s_cnt[t + i * P1_THREADS] = 0;
    __syncthreads();

    const long base = (long)blockIdx.x * WAVE;
    #pragma unroll
    for (int c = 0; c < WAVE / (P1_THREADS * 4); c++) {
        long e0 = base + (long)c * (P1_THREADS * 4) + (long)t * 4;
        if (e0 + 3 < E) {
            int4 s4 = *reinterpret_cast<const int4*>(&src[e0]);
            int4 d4 = *reinterpret_cast<const int4*>(&dst[e0]);
            int4 p4 = *reinterpret_cast<const int4*>(&plen[e0]);
            stage_edge(e0 + 0, s4.x, d4.x, p4.x, s_stage, s_cnt);
            stage_edge(e0 + 1, s4.y, d4.y, p4.y, s_stage, s_cnt);
            stage_edge(e0 + 2, s4.z, d4.z, p4.z, s_stage, s_cnt);
            stage_edge(e0 + 3, s4.w, d4.w, p4.w, s_stage, s_cnt);
        } else {
            for (long e = e0; e < E && e < e0 + 4; e++)
                stage_edge(e, src[e], dst[e], plen[e], s_stage, s_cnt);
        }
    }
    __syncthreads();

    // pair-packed flush: thread-per-bucket (full lane occupancy, ATOMG
    // latency overlapped across threads), 16B stores = 2 records each
    #pragma unroll
    for (int i = 0; i < BUCKETS / P1_THREADS; i++) {
        int bk = t + i * P1_THREADS;
        int k = min(s_cnt[bk], STAGE_CAP);
        if (k > 0) {
            int p  = (k + 1) >> 1;                       // pairs (<=3)
            int gp = atomicAdd(&g_cur[bk * 8], p);
            const unsigned long long* sp = &s_stage[bk * STAGE_CAP];
            uint4* dp = &g_bin[(size_t)bk * CAP_PAIRS + gp];
            #pragma unroll
            for (int j = 0; j < (STAGE_CAP + 1) / 2; j++) {
                if (j < p && gp + j < CAP_PAIRS) {
                    unsigned long long r0 = sp[2 * j];
                    unsigned long long r1 = (2 * j + 1 < k) ? sp[2 * j + 1] : 0ull;
                    dp[j] = make_uint4((unsigned int)r0, (unsigned int)(r0 >> 32),
                                       (unsigned int)r1, (unsigned int)(r1 >> 32));
                }
            }
        }
    }
}

// ---------------- Pass 2: per-bucket resolve + convert ----------------
__global__ void __launch_bounds__(P2_THREADS, 3)
resolve_kernel(const float* __restrict__ b,
               float* __restrict__ out) {
    extern __shared__ char smem[];
    unsigned int* s_key = (unsigned int*)smem;          // 2*8192*4 = 64KB
    __shared__ float s_b[8];

    const int bk = blockIdx.x;
    const int t  = threadIdx.x;

    // zero 64KB of keys (uint4)
    uint4* kz = (uint4*)s_key;
    #pragma unroll
    for (int i = 0; i < (2 * N_NODES / 4) / P2_THREADS; i++)
        kz[t + i * P2_THREADS] = make_uint4(0u, 0u, 0u, 0u);
    if (t < 8) s_b[t] = (t < 5) ? b[t] : 0.0f;

    int cnt = g_cur[bk * 8];                            // pairs
    if (cnt > CAP_PAIRS) cnt = CAP_PAIRS;
    __syncthreads();

    // stream pairs; predicate atomics on key!=0 (padding is free)
    const uint4* __restrict__ recs4 = &g_bin[(size_t)bk * CAP_PAIRS];
    for (int i = t; i < cnt; i += P2_THREADS) {
        uint4 r = recs4[i];
        if (r.x) atomicMax(&s_key[r.y & 0x3FFFu], r.x);
        if (r.z) atomicMax(&s_key[r.w & 0x3FFFu], r.z);
    }
    __syncthreads();

    // convert + contiguous 64KB output write (rows bk*2, bk*2+1)
    float* __restrict__ ob = out + (size_t)bk * 2 * N_NODES;
    #pragma unroll
    for (int i = 0; i < (2 * N_NODES / 4) / P2_THREADS; i++) {
        int j4 = t + i * P2_THREADS;
        uint4 k = kz[j4];
        float4 o;
        o.x = k.x ? s_b[k.x & 7u] : 0.0f;
        o.y = k.y ? s_b[k.y & 7u] : 0.0f;
        o.z = k.z ? s_b[k.z & 7u] : 0.0f;
        o.w = k.w ? s_b[k.w & 7u] : 0.0f;
        *reinterpret_cast<float4*>(&ob[j4 * 4]) = o;
    }

    // reset our cursor for the next graph replay (deterministic counts)
    if (t == 0) g_cur[bk * 8] = 0;
}

extern "C" void kernel_launch(void* const* d_in, const int* in_sizes, int n_in,
                              void* d_out, int out_size) {
    // metadata order: x [N,128] f32, src [E] i32, dst [E] i32,
    //                 path_len [E] i32, b [5] f32
    const int*   src  = (const int*)d_in[1];
    const int*   dst  = (const int*)d_in[2];
    const int*   plen = (const int*)d_in[3];
    const float* b    = (const float*)d_in[4];
    float*       out  = (float*)d_out;

    const long E = (long)in_sizes[1];   // 8,000,000

    const size_t p1_smem = (size_t)BUCKETS * STAGE_CAP * 8 + BUCKETS * 4;  // 208KB
    const size_t p2_smem = (size_t)2 * N_NODES * 4;                        // 64KB

    static bool attr_set = false;
    if (!attr_set) {
        cudaFuncSetAttribute(bin_kernel,
                             cudaFuncAttributeMaxDynamicSharedMemorySize, (int)p1_smem);
        cudaFuncSetAttribute(resolve_kernel,
                             cudaFuncAttributeMaxDynamicSharedMemorySize, (int)p2_smem);
        attr_set = true;
    }

    {
        const int blocks = (int)((E + WAVE - 1) / WAVE);   // 977
        bin_kernel<<<blocks, P1_THREADS, p1_smem>>>(src, dst, plen, E);
    }
    {
        resolve_kernel<<<BUCKETS, P2_THREADS, p2_smem>>>(b, out);
    }
}